// round 8
// baseline (speedup 1.0000x reference)
#include <cuda_runtime.h>
#include <cuda_bf16.h>
#include <cstdint>

#define D 128
#define NMAX 50048
#define EMAX 800000
#define RPB 8   // rows per gemm block

// Scratch (static device arrays; no allocation anywhere)
__device__ float g_h[(size_t)NMAX * D];     // per-layer transformed features
__device__ float g_agg[(size_t)NMAX * D];   // layer-1 aggregated output
__device__ float g_dinv[NMAX];              // rsqrt(deg+1)
__device__ int   g_deg[NMAX];
__device__ int   g_off[NMAX + 1];           // CSR row offsets (by dst)
__device__ int   g_cur[NMAX];               // fill cursors
__device__ int   g_src[EMAX];
__device__ int   g_dst[EMAX];
__device__ int2  g_ce[EMAX];                // CSR entries: (src, bits(dinv[src]))

__global__ void k_zero_deg(int n) {
    int i = blockIdx.x * blockDim.x + threadIdx.x;
    if (i < n) g_deg[i] = 0;
}

// decode edges (int64 or int32, detected per-block) + degree count
__global__ void k_decode(const void* __restrict__ ei, int E, int n) {
    __shared__ int s_is64;
    if (threadIdx.x == 0) {
        const int* p = (const int*)ei;
        int az = 1;
        #pragma unroll
        for (int i = 1; i < 32; i += 2)
            if (p[i] != 0) az = 0;
        s_is64 = az;
    }
    __syncthreads();

    int i = blockIdx.x * blockDim.x + threadIdx.x;
    if (i >= E) return;
    int s, d;
    if (s_is64) {
        const long long* p = (const long long*)ei;
        s = (int)p[i];
        d = (int)p[(size_t)E + i];
    } else {
        const int* p = (const int*)ei;
        s = p[i];
        d = p[E + i];
    }
    s = min(max(s, 0), n - 1);
    d = min(max(d, 0), n - 1);
    g_src[i] = s;
    g_dst[i] = d;
    atomicAdd(&g_deg[d], 1);
}

// ---------------------------------------------------------------------------
// single-block exclusive scan of g_deg -> g_off/g_cur, plus dinv = rsqrt(deg+1)
// ---------------------------------------------------------------------------
__global__ void k_scan(int n) {
    __shared__ int warp_sums[32];
    const int t = threadIdx.x;                 // 1024 threads
    const int chunk = (n + 1023) >> 10;
    const int begin = t * chunk;
    const int end   = min(begin + chunk, n);

    int s = 0;
    for (int i = begin; i < end; i++) s += g_deg[i];

    const int lane = t & 31, w = t >> 5;
    int v = s;
    #pragma unroll
    for (int o = 1; o < 32; o <<= 1) {
        int x = __shfl_up_sync(0xFFFFFFFFu, v, o);
        if (lane >= o) v += x;
    }
    if (lane == 31) warp_sums[w] = v;
    __syncthreads();
    if (w == 0) {
        int ws = warp_sums[lane];
        #pragma unroll
        for (int o = 1; o < 32; o <<= 1) {
            int x = __shfl_up_sync(0xFFFFFFFFu, ws, o);
            if (lane >= o) ws += x;
        }
        warp_sums[lane] = ws;
    }
    __syncthreads();
    int run = (v - s) + (w > 0 ? warp_sums[w - 1] : 0);

    for (int i = begin; i < end; i++) {
        int dg = g_deg[i];
        g_off[i] = run;
        g_cur[i] = run;
        g_dinv[i] = rsqrtf((float)dg + 1.0f);
        run += dg;
    }
    if (end == n && begin < n) g_off[n] = run;
}

// ---------------------------------------------------------------------------
// device bodies (shared by plain and fused kernels)
// ---------------------------------------------------------------------------
__device__ __forceinline__ void fill_body(int i, int E) {
    if (i >= E) return;
    int s = g_src[i];
    int pos = atomicAdd(&g_cur[g_dst[i]], 1);
    g_ce[pos] = make_int2(s, __float_as_int(g_dinv[s]));
}

// GEMM body (R4-proven): g_h[row][j] = sum_k in'[row][k] * W[k][j]
// blockDim.x = 128 (one thread per output column), RPB rows per tile.
__device__ __forceinline__ void gemm_body(const float* __restrict__ in,
                                          const float* __restrict__ W,
                                          int relu_in, int n, int tile)
{
    __shared__ float s[D][RPB];   // transposed: s[k][r]
    const int t = threadIdx.x;
    const int row0 = tile * RPB;

#pragma unroll
    for (int r = 0; r < RPB; r++) {
        int row = row0 + r;
        float v = 0.0f;
        if (row < n) {
            v = in[(size_t)row * D + t];
            if (relu_in) v = fmaxf(v, 0.0f);
        }
        s[t][r] = v;
    }
    __syncthreads();

    float acc[RPB];
#pragma unroll
    for (int r = 0; r < RPB; r++) acc[r] = 0.0f;

#pragma unroll 4
    for (int k = 0; k < D; k++) {
        float w = W[k * D + t];                 // coalesced across threads
        float4 a0 = *(const float4*)&s[k][0];   // broadcast LDS.128
        float4 a1 = *(const float4*)&s[k][4];
        acc[0] = fmaf(a0.x, w, acc[0]);
        acc[1] = fmaf(a0.y, w, acc[1]);
        acc[2] = fmaf(a0.z, w, acc[2]);
        acc[3] = fmaf(a0.w, w, acc[3]);
        acc[4] = fmaf(a1.x, w, acc[4]);
        acc[5] = fmaf(a1.y, w, acc[5]);
        acc[6] = fmaf(a1.z, w, acc[6]);
        acc[7] = fmaf(a1.w, w, acc[7]);
    }

#pragma unroll
    for (int r = 0; r < RPB; r++) {
        int row = row0 + r;
        if (row >= n) break;
        g_h[(size_t)row * D + t] = acc[r];
    }
}

// fused: layer-1 GEMM + CSR fill (independent work, one launch)
__global__ void k_gemm1_fill(const float* __restrict__ x,
                             const float* __restrict__ W1,
                             int n, int E, int gemm_blocks)
{
    if ((int)blockIdx.x < gemm_blocks) {
        gemm_body(x, W1, 0, n, blockIdx.x);
    } else {
        int i = ((int)blockIdx.x - gemm_blocks) * (int)blockDim.x + (int)threadIdx.x;
        fill_body(i, E);
    }
}

__global__ void k_gemm(const float* __restrict__ x_or_null,
                       const float* __restrict__ W,
                       int relu_in, int n)
{
    const float* in = x_or_null ? x_or_null : g_agg;
    gemm_body(in, W, relu_in, n, blockIdx.x);
}

// ---------------------------------------------------------------------------
// Gather-aggregate: one warp per dst row, lane owns one float4 of 128 cols.
// out[d] = dinv[d] * sum_{e in CSR[d]} dinv[src]*h[src] + dinv[d]^2*h[d] + b
// Predicated unroll-4: no serial tail, 4 gathers always in flight,
// 4 independent accumulators (1-deep FMA chains).
// ---------------------------------------------------------------------------
__global__ void k_agg(float* __restrict__ out_or_null,
                      const float* __restrict__ b, int n)
{
    float* out = out_or_null ? out_or_null : g_agg;

    const int warp = (blockIdx.x * blockDim.x + threadIdx.x) >> 5;
    const int lane = threadIdx.x & 31;
    if (warp >= n) return;

    const int d   = warp;
    const int beg = g_off[d];
    const int end = g_off[d + 1];

    float4 a0 = make_float4(0.f, 0.f, 0.f, 0.f);
    float4 a1 = a0, a2 = a0, a3 = a0;

    for (int j = beg; j < end; j += 4) {
        int j1 = j + 1, j2 = j + 2, j3 = j + 3;
        int2 e0 = g_ce[j];
        int2 e1 = g_ce[j1 < end ? j1 : beg];
        int2 e2 = g_ce[j2 < end ? j2 : beg];
        int2 e3 = g_ce[j3 < end ? j3 : beg];
        float w0 = __int_as_float(e0.y);
        float w1 = j1 < end ? __int_as_float(e1.y) : 0.0f;
        float w2 = j2 < end ? __int_as_float(e2.y) : 0.0f;
        float w3 = j3 < end ? __int_as_float(e3.y) : 0.0f;
        const float4 v0 = *(const float4*)&g_h[(size_t)e0.x * D + lane * 4];
        const float4 v1 = *(const float4*)&g_h[(size_t)e1.x * D + lane * 4];
        const float4 v2 = *(const float4*)&g_h[(size_t)e2.x * D + lane * 4];
        const float4 v3 = *(const float4*)&g_h[(size_t)e3.x * D + lane * 4];
        a0.x = fmaf(w0, v0.x, a0.x); a0.y = fmaf(w0, v0.y, a0.y);
        a0.z = fmaf(w0, v0.z, a0.z); a0.w = fmaf(w0, v0.w, a0.w);
        a1.x = fmaf(w1, v1.x, a1.x); a1.y = fmaf(w1, v1.y, a1.y);
        a1.z = fmaf(w1, v1.z, a1.z); a1.w = fmaf(w1, v1.w, a1.w);
        a2.x = fmaf(w2, v2.x, a2.x); a2.y = fmaf(w2, v2.y, a2.y);
        a2.z = fmaf(w2, v2.z, a2.z); a2.w = fmaf(w2, v2.w, a2.w);
        a3.x = fmaf(w3, v3.x, a3.x); a3.y = fmaf(w3, v3.y, a3.y);
        a3.z = fmaf(w3, v3.z, a3.z); a3.w = fmaf(w3, v3.w, a3.w);
    }

    float4 acc;
    acc.x = (a0.x + a1.x) + (a2.x + a3.x);
    acc.y = (a0.y + a1.y) + (a2.y + a3.y);
    acc.z = (a0.z + a1.z) + (a2.z + a3.z);
    acc.w = (a0.w + a1.w) + (a2.w + a3.w);

    const float di  = g_dinv[d];
    const float di2 = di * di;
    const float4 hv = *(const float4*)&g_h[(size_t)d * D + lane * 4];
    const float4 bv = *(const float4*)&b[lane * 4];

    float4 o;
    o.x = fmaf(di, acc.x, fmaf(di2, hv.x, bv.x));
    o.y = fmaf(di, acc.y, fmaf(di2, hv.y, bv.y));
    o.z = fmaf(di, acc.z, fmaf(di2, hv.z, bv.z));
    o.w = fmaf(di, acc.w, fmaf(di2, hv.w, bv.w));
    *(float4*)&out[(size_t)d * D + lane * 4] = o;
}

// ---------------------------------------------------------------------------
// launch
// ---------------------------------------------------------------------------
extern "C" void kernel_launch(void* const* d_in, const int* in_sizes, int n_in,
                              void* d_out, int out_size)
{
    const float* x   = (const float*)d_in[0];
    const void*  ei  = d_in[1];
    const float* W1  = (const float*)d_in[2];
    const float* b1  = (const float*)d_in[3];
    const float* W2  = (const float*)d_in[4];
    const float* b2  = (const float*)d_in[5];
    float*       out = (float*)d_out;

    const int N = in_sizes[0] / D;
    const int E = in_sizes[1] / 2;

    const int TPB = 256;
    const int eb  = (E + TPB - 1) / TPB;
    const int nb  = (N + TPB - 1) / TPB;

    // preprocessing chain: zero -> decode(+count) -> scan(+dinv)
    k_zero_deg<<<nb, TPB>>>(N);
    k_decode<<<eb, TPB>>>(ei, E, N);
    k_scan<<<1, 1024>>>(N);

    const int gemm_blocks = (N + RPB - 1) / RPB;
    const int fill_blocks = (E + D - 1) / D;            // blockDim=128 for fused
    const int agg_blocks  = (N * 32 + TPB - 1) / TPB;   // one warp per row

    // layer 1 GEMM fused with CSR fill (independent): h1 = x @ W1 ; build g_ce
    k_gemm1_fill<<<gemm_blocks + fill_blocks, D>>>(x, W1, N, E, gemm_blocks);
    // agg1 = gather(h1) + b1
    k_agg<<<agg_blocks, TPB>>>(nullptr, b1, N);

    // layer 2: h2 = relu(agg1) @ W2 ; out = gather(h2) + b2
    k_gemm<<<gemm_blocks, D>>>(nullptr, W2, 1, N);
    k_agg<<<agg_blocks, TPB>>>(out, b2, N);
}

// round 9
// speedup vs baseline: 1.1142x; 1.1142x over previous
#include <cuda_runtime.h>
#include <cuda_bf16.h>
#include <cstdint>

#define D 128
#define NMAX 50048
#define EMAX 800000
#define TM 32            // rows per gemm block

// Scratch (static device arrays; no allocation anywhere)
__device__ float g_h[(size_t)NMAX * D];     // per-layer transformed features
__device__ float g_agg[(size_t)NMAX * D];   // layer-1 aggregated output
__device__ float g_dinv[NMAX];              // rsqrt(deg+1)
__device__ int   g_deg[NMAX];
__device__ int   g_off[NMAX + 1];           // CSR row offsets (by dst)
__device__ int   g_cur[NMAX];               // fill cursors
__device__ int   g_src[EMAX];
__device__ int   g_dst[EMAX];
__device__ int2  g_ce[EMAX];                // CSR entries: (src, bits(dinv[src]))

__global__ void k_zero_deg(int n) {
    int i = blockIdx.x * blockDim.x + threadIdx.x;
    if (i < n) g_deg[i] = 0;
}

// decode edges (int64 or int32, detected per-block) + degree count
__global__ void k_decode(const void* __restrict__ ei, int E, int n) {
    __shared__ int s_is64;
    if (threadIdx.x == 0) {
        const int* p = (const int*)ei;
        int az = 1;
        #pragma unroll
        for (int i = 1; i < 32; i += 2)
            if (p[i] != 0) az = 0;
        s_is64 = az;
    }
    __syncthreads();

    int i = blockIdx.x * blockDim.x + threadIdx.x;
    if (i >= E) return;
    int s, d;
    if (s_is64) {
        const long long* p = (const long long*)ei;
        s = (int)p[i];
        d = (int)p[(size_t)E + i];
    } else {
        const int* p = (const int*)ei;
        s = p[i];
        d = p[E + i];
    }
    s = min(max(s, 0), n - 1);
    d = min(max(d, 0), n - 1);
    g_src[i] = s;
    g_dst[i] = d;
    atomicAdd(&g_deg[d], 1);
}

// ---------------------------------------------------------------------------
// single-block exclusive scan of g_deg -> g_off/g_cur, plus dinv = rsqrt(deg+1)
// ---------------------------------------------------------------------------
__global__ void k_scan(int n) {
    __shared__ int warp_sums[32];
    const int t = threadIdx.x;                 // 1024 threads
    const int chunk = (n + 1023) >> 10;
    const int begin = t * chunk;
    const int end   = min(begin + chunk, n);

    int s = 0;
    for (int i = begin; i < end; i++) s += g_deg[i];

    const int lane = t & 31, w = t >> 5;
    int v = s;
    #pragma unroll
    for (int o = 1; o < 32; o <<= 1) {
        int x = __shfl_up_sync(0xFFFFFFFFu, v, o);
        if (lane >= o) v += x;
    }
    if (lane == 31) warp_sums[w] = v;
    __syncthreads();
    if (w == 0) {
        int ws = warp_sums[lane];
        #pragma unroll
        for (int o = 1; o < 32; o <<= 1) {
            int x = __shfl_up_sync(0xFFFFFFFFu, ws, o);
            if (lane >= o) ws += x;
        }
        warp_sums[lane] = ws;
    }
    __syncthreads();
    int run = (v - s) + (w > 0 ? warp_sums[w - 1] : 0);

    for (int i = begin; i < end; i++) {
        int dg = g_deg[i];
        g_off[i] = run;
        g_cur[i] = run;
        g_dinv[i] = rsqrtf((float)dg + 1.0f);
        run += dg;
    }
    if (end == n && begin < n) g_off[n] = run;
}

// fill CSR: entry = (src, dinv[src])
__global__ void k_fill(int E) {
    int i = blockIdx.x * blockDim.x + threadIdx.x;
    if (i >= E) return;
    int s = g_src[i];
    int pos = atomicAdd(&g_cur[g_dst[i]], 1);
    g_ce[pos] = make_int2(s, __float_as_int(g_dinv[s]));
}

// ---------------------------------------------------------------------------
// Register-blocked GEMM: 32 rows x 128 cols per 128-thread block.
// Thread (rg = t>>5, cg = t&31) computes rows rg*8..rg*8+7, cols cg*4..cg*4+3.
// Per k: 1 LDG.128 (W) + 2 broadcast LDS.128 (rows) + 32 FMA.
//   in' = relu(in) if relu_in; in = x_or_null ?: g_agg
// ---------------------------------------------------------------------------
__global__ void __launch_bounds__(128)
k_gemm(const float* __restrict__ x_or_null,
       const float* __restrict__ W,
       int relu_in, int n)
{
    const float* in = x_or_null ? x_or_null : g_agg;

    __shared__ float s[D][36];    // s[k][row]; pad 36 -> 16B-aligned rows
    const int t   = threadIdx.x;  // 0..127 (staging: column index)
    const int rg  = t >> 5;       // 0..3
    const int cg  = t & 31;       // 0..31
    const int row0 = blockIdx.x * TM;

    // stage 32 rows (transposed): s[k][r] = in'[row0+r][k]
#pragma unroll 8
    for (int r = 0; r < TM; r++) {
        int row = row0 + r;
        float v = 0.0f;
        if (row < n) {
            v = in[(size_t)row * D + t];
            if (relu_in) v = fmaxf(v, 0.0f);
        }
        s[t][r] = v;
    }
    __syncthreads();

    float acc[8][4];
#pragma unroll
    for (int r = 0; r < 8; r++)
#pragma unroll
        for (int c = 0; c < 4; c++) acc[r][c] = 0.0f;

    const int rbase = rg * 8;

#pragma unroll 4
    for (int k = 0; k < D; k++) {
        const float4 wv = *(const float4*)&W[k * D + (cg << 2)];   // coalesced
        const float4 a0 = *(const float4*)&s[k][rbase];            // broadcast
        const float4 a1 = *(const float4*)&s[k][rbase + 4];        // broadcast
        const float ar[8] = {a0.x, a0.y, a0.z, a0.w, a1.x, a1.y, a1.z, a1.w};
#pragma unroll
        for (int r = 0; r < 8; r++) {
            acc[r][0] = fmaf(ar[r], wv.x, acc[r][0]);
            acc[r][1] = fmaf(ar[r], wv.y, acc[r][1]);
            acc[r][2] = fmaf(ar[r], wv.z, acc[r][2]);
            acc[r][3] = fmaf(ar[r], wv.w, acc[r][3]);
        }
    }

#pragma unroll
    for (int r = 0; r < 8; r++) {
        int row = row0 + rbase + r;
        if (row < n) {
            float4 o = make_float4(acc[r][0], acc[r][1], acc[r][2], acc[r][3]);
            *(float4*)&g_h[(size_t)row * D + (cg << 2)] = o;       // coalesced
        }
    }
}

// ---------------------------------------------------------------------------
// Gather-aggregate (R4-proven): one warp per dst row, lane owns one float4.
// out[d] = dinv[d] * sum_{e in CSR[d]} dinv[src]*h[src] + dinv[d]^2*h[d] + b
// ---------------------------------------------------------------------------
__global__ void k_agg(float* __restrict__ out_or_null,
                      const float* __restrict__ b, int n)
{
    float* out = out_or_null ? out_or_null : g_agg;

    const int warp = (blockIdx.x * blockDim.x + threadIdx.x) >> 5;
    const int lane = threadIdx.x & 31;
    if (warp >= n) return;

    const int d   = warp;
    const int beg = g_off[d];
    const int end = g_off[d + 1];

    float4 acc = make_float4(0.f, 0.f, 0.f, 0.f);
    int j = beg;
    for (; j + 2 <= end; j += 2) {            // unroll x2 for load MLP
        int2 e0 = __ldg(&g_ce[j]);
        int2 e1 = __ldg(&g_ce[j + 1]);
        float w0 = __int_as_float(e0.y);
        float w1 = __int_as_float(e1.y);
        const float4 v0 = *(const float4*)&g_h[(size_t)e0.x * D + lane * 4];
        const float4 v1 = *(const float4*)&g_h[(size_t)e1.x * D + lane * 4];
        acc.x = fmaf(w0, v0.x, fmaf(w1, v1.x, acc.x));
        acc.y = fmaf(w0, v0.y, fmaf(w1, v1.y, acc.y));
        acc.z = fmaf(w0, v0.z, fmaf(w1, v1.z, acc.z));
        acc.w = fmaf(w0, v0.w, fmaf(w1, v1.w, acc.w));
    }
    if (j < end) {
        int2 e = __ldg(&g_ce[j]);
        float w = __int_as_float(e.y);
        const float4 v = *(const float4*)&g_h[(size_t)e.x * D + lane * 4];
        acc.x = fmaf(w, v.x, acc.x);
        acc.y = fmaf(w, v.y, acc.y);
        acc.z = fmaf(w, v.z, acc.z);
        acc.w = fmaf(w, v.w, acc.w);
    }

    const float di  = g_dinv[d];
    const float di2 = di * di;
    const float4 hv = *(const float4*)&g_h[(size_t)d * D + lane * 4];
    const float4 bv = *(const float4*)&b[lane * 4];

    float4 o;
    o.x = fmaf(di, acc.x, fmaf(di2, hv.x, bv.x));
    o.y = fmaf(di, acc.y, fmaf(di2, hv.y, bv.y));
    o.z = fmaf(di, acc.z, fmaf(di2, hv.z, bv.z));
    o.w = fmaf(di, acc.w, fmaf(di2, hv.w, bv.w));
    *(float4*)&out[(size_t)d * D + lane * 4] = o;
}

// ---------------------------------------------------------------------------
// launch
// ---------------------------------------------------------------------------
extern "C" void kernel_launch(void* const* d_in, const int* in_sizes, int n_in,
                              void* d_out, int out_size)
{
    const float* x   = (const float*)d_in[0];
    const void*  ei  = d_in[1];
    const float* W1  = (const float*)d_in[2];
    const float* b1  = (const float*)d_in[3];
    const float* W2  = (const float*)d_in[4];
    const float* b2  = (const float*)d_in[5];
    float*       out = (float*)d_out;

    const int N = in_sizes[0] / D;
    const int E = in_sizes[1] / 2;

    const int TPB = 256;
    const int eb  = (E + TPB - 1) / TPB;
    const int nb  = (N + TPB - 1) / TPB;

    // preprocessing: zero -> decode(+count) -> scan(+dinv) -> CSR fill
    k_zero_deg<<<nb, TPB>>>(N);
    k_decode<<<eb, TPB>>>(ei, E, N);
    k_scan<<<1, 1024>>>(N);
    k_fill<<<eb, TPB>>>(E);

    const int gemm_blocks = (N + TM - 1) / TM;
    const int agg_blocks  = (N * 32 + TPB - 1) / TPB;   // one warp per row

    // layer 1: h1 = x @ W1 ; agg1 = gather(h1) + b1
    k_gemm<<<gemm_blocks, 128>>>(x, W1, 0, N);
    k_agg<<<agg_blocks, TPB>>>(nullptr, b1, N);

    // layer 2: h2 = relu(agg1) @ W2 ; out = gather(h2) + b2
    k_gemm<<<gemm_blocks, 128>>>(nullptr, W2, 1, N);
    k_agg<<<agg_blocks, TPB>>>(out, b2, N);
}